// round 9
// baseline (speedup 1.0000x reference)
#include <cuda_runtime.h>
#include <cuda_bf16.h>

// out[n, p] = sum_f matrix[p, f] * g[f],  g = (field[b].x, field[b].w, field[b].y, field[b].z)
// b = batch[n].  P = 32 -> each node owns one full 128B output line (8 x float4).
// positions input is dead code in the reference (its einsum result is discarded).

__global__ void __launch_bounds__(256)
dgto_proj_kernel(const int* __restrict__ batch,
                 const float4* __restrict__ field,
                 const float4* __restrict__ matrix,
                 float4* __restrict__ out,
                 int n)
{
    __shared__ float4 Ms[32];           // matrix rows, 512 B
    if (threadIdx.x < 32) Ms[threadIdx.x] = matrix[threadIdx.x];

    int i = blockIdx.x * blockDim.x + threadIdx.x;

    // Issue the gather chain before the barrier so the L2 round-trip overlaps
    // with the shared-mem staging.
    float4 f = make_float4(0.f, 0.f, 0.f, 0.f);
    if (i < n) {
        int b = batch[i];               // coalesced 4B load
        f = __ldg(&field[b]);           // 16B gather, L2-resident (1.6 MB working set)
    }
    __syncthreads();
    if (i >= n) return;

    // permutation [0,3,1,2]
    float g0 = f.x, g1 = f.w, g2 = f.y, g3 = f.z;

    float4* o = out + (size_t)i * 8;    // 128B-aligned, thread-private line

#pragma unroll
    for (int q = 0; q < 8; q++) {
        float4 m0 = Ms[q * 4 + 0];
        float4 m1 = Ms[q * 4 + 1];
        float4 m2 = Ms[q * 4 + 2];
        float4 m3 = Ms[q * 4 + 3];
        float4 r;
        r.x = fmaf(m0.x, g0, fmaf(m0.y, g1, fmaf(m0.z, g2, m0.w * g3)));
        r.y = fmaf(m1.x, g0, fmaf(m1.y, g1, fmaf(m1.z, g2, m1.w * g3)));
        r.z = fmaf(m2.x, g0, fmaf(m2.y, g1, fmaf(m2.z, g2, m2.w * g3)));
        r.w = fmaf(m3.x, g0, fmaf(m3.y, g1, fmaf(m3.z, g2, m3.w * g3)));
        __stcs(&o[q], r);               // evict-first streaming store: never re-read
    }
}

extern "C" void kernel_launch(void* const* d_in, const int* in_sizes, int n_in,
                              void* d_out, int out_size)
{
    // metadata order: batch (int32), positions (float32, UNUSED), field (float32), matrix (float32)
    const int*    batch  = (const int*)d_in[0];
    const float4* field  = (const float4*)d_in[2];
    const float4* matrix = (const float4*)d_in[3];
    float4*       out    = (float4*)d_out;

    int n = in_sizes[0];
    int n_from_out = out_size / 32;     // P = 32 floats per node
    if (n_from_out > 0 && n_from_out < n) n = n_from_out;

    int threads = 256;
    int blocks = (n + threads - 1) / threads;
    dgto_proj_kernel<<<blocks, threads>>>(batch, field, matrix, out, n);
}

// round 15
// speedup vs baseline: 1.1074x; 1.1074x over previous
#include <cuda_runtime.h>
#include <cuda_bf16.h>

// Reference reduces to: out[n, p] = c[p] * g_p(field[batch[n]]) where matrix@perm
// has exactly ONE nonzero per row:
//   p in [0,8)      : col 0 -> f.x
//   p = 8+3s+0      : col 3 -> f.z
//   p = 8+3s+1      : col 1 -> f.w
//   p = 8+3s+2      : col 2 -> f.y
// positions input is dead code. P=32 -> each node owns one 128B output line.

__device__ __forceinline__ float sel_g(int p, const float4& f) {
    if (p < 8) return f.x;
    int k = (p - 8) % 3;
    return (k == 0) ? f.z : ((k == 1) ? f.w : f.y);
}

__global__ void __launch_bounds__(256)
dgto_proj_kernel(const int* __restrict__ batch,
                 const float4* __restrict__ field,
                 const float* __restrict__ matrix,
                 float4* __restrict__ out,
                 int n)
{
    __shared__ float cs[32];            // packed per-row nonzero coefficients
    if (threadIdx.x < 32) {
        int p = threadIdx.x;
        int k = (p >= 8) ? (p - 8) % 3 : 0;
        int col = (p < 8) ? 0 : ((k == 0) ? 3 : ((k == 1) ? 1 : 2));
        cs[p] = matrix[p * 4 + col];
    }
    __syncthreads();

    int t  = blockIdx.x * blockDim.x + threadIdx.x;
    int i0 = t * 2;                     // 2 nodes per thread
    if (i0 >= n) return;
    bool two = (i0 + 1 < n);

    // batch indices (8B-aligned int2 since i0 is even)
    int2 bb;
    if (two) bb = ((const int2*)batch)[t];
    else { bb.x = batch[i0]; bb.y = bb.x; }

    // two independent L2-resident gathers in flight (MLP=2)
    float4 f0 = __ldg(&field[bb.x]);
    float4 f1 = __ldg(&field[bb.y]);

    // coefficients -> 8 float4 registers (8 broadcast LDS.128, once per thread)
    float4 C[8];
#pragma unroll
    for (int q = 0; q < 8; q++) C[q] = reinterpret_cast<const float4*>(cs)[q];

    float4* o0 = out + (size_t)i0 * 8;  // 128B-aligned private line

#pragma unroll
    for (int q = 0; q < 8; q++) {
        int p = q * 4;
        float4 r;
        r.x = C[q].x * sel_g(p + 0, f0);
        r.y = C[q].y * sel_g(p + 1, f0);
        r.z = C[q].z * sel_g(p + 2, f0);
        r.w = C[q].w * sel_g(p + 3, f0);
        __stcs(&o0[q], r);              // evict-first streaming store
    }

    if (two) {
        float4* o1 = o0 + 8;
#pragma unroll
        for (int q = 0; q < 8; q++) {
            int p = q * 4;
            float4 r;
            r.x = C[q].x * sel_g(p + 0, f1);
            r.y = C[q].y * sel_g(p + 1, f1);
            r.z = C[q].z * sel_g(p + 2, f1);
            r.w = C[q].w * sel_g(p + 3, f1);
            __stcs(&o1[q], r);
        }
    }
}

extern "C" void kernel_launch(void* const* d_in, const int* in_sizes, int n_in,
                              void* d_out, int out_size)
{
    // metadata order: batch (int32), positions (float32, UNUSED), field (float32), matrix (float32)
    const int*    batch  = (const int*)d_in[0];
    const float4* field  = (const float4*)d_in[2];
    const float*  matrix = (const float*)d_in[3];
    float4*       out    = (float4*)d_out;

    int n = in_sizes[0];
    int n_from_out = out_size / 32;      // P = 32 floats per node
    if (n_from_out > 0 && n_from_out < n) n = n_from_out;

    int threads = 256;
    int nodes_per_block = threads * 2;
    int blocks = (n + nodes_per_block - 1) / nodes_per_block;
    dgto_proj_kernel<<<blocks, threads>>>(batch, field, matrix, out, n);
}